// round 15
// baseline (speedup 1.0000x reference)
#include <cuda_runtime.h>
#include <cuda_bf16.h>
#include <cstdint>

#define B_ 4
#define H_ 8
#define N_ 2048
#define D_ 64
#define KTOP 16
#define FSCALE (1.0f/64.0f)
#define MARGIN 0.08f
#define NCAND 96

#define NIT 8               // 512 / BK, BK=64 (one head per iter)
#define STAGE_BYTES 32768   // A tile 16KB + B tile 16KB
#define SMEM_TOTAL (2 * STAGE_BYTES)   // 64KB -> 2 CTAs/SM

// ---- global scratch (allocation-free rule: __device__ globals) ----
__device__ unsigned short g_zb[(size_t)B_ * N_ * N_];   // z_approx bf16 bits
__device__ __nv_bfloat16 g_qs[(size_t)B_ * H_ * N_ * D_];
__device__ __nv_bfloat16 g_ks[(size_t)B_ * H_ * N_ * D_];

// ---------------------------------------------------------------------------
// helpers
// ---------------------------------------------------------------------------
__device__ __forceinline__ uint32_t smem_to_u32(const void* p) {
    uint32_t a;
    asm("{ .reg .u64 t; cvta.to.shared.u64 t, %1; cvt.u32.u64 %0, t; }" : "=r"(a) : "l"(p));
    return a;
}
__device__ __forceinline__ uint32_t tile_off(int row, int chunk) {
    return (uint32_t)(row * 128 + ((chunk ^ (row & 7)) << 4));
}
__device__ __forceinline__ void cp16(uint32_t dst, const void* src) {
    asm volatile("cp.async.cg.shared.global [%0], [%1], 16;" :: "r"(dst), "l"(src) : "memory");
}
__device__ __forceinline__ void cp_commit() {
    asm volatile("cp.async.commit_group;" ::: "memory");
}
template<int Ng> __device__ __forceinline__ void cp_wait() {
    asm volatile("cp.async.wait_group %0;" :: "n"(Ng) : "memory");
}
__device__ __forceinline__ void ldsm4(uint32_t* r, uint32_t addr) {
    asm volatile("ldmatrix.sync.aligned.m8n8.x4.shared.b16 {%0,%1,%2,%3}, [%4];"
                 : "=r"(r[0]), "=r"(r[1]), "=r"(r[2]), "=r"(r[3]) : "r"(addr));
}
__device__ __forceinline__ void mma_bf16(float* c, const uint32_t* a,
                                         uint32_t b0, uint32_t b1) {
    asm volatile(
        "mma.sync.aligned.m16n8k16.row.col.f32.bf16.bf16.f32 "
        "{%0,%1,%2,%3}, {%4,%5,%6,%7}, {%8,%9}, {%0,%1,%2,%3};"
        : "+f"(c[0]), "+f"(c[1]), "+f"(c[2]), "+f"(c[3])
        : "r"(a[0]), "r"(a[1]), "r"(a[2]), "r"(a[3]), "r"(b0), "r"(b1));
}
// accurate gumbel (exact refine path only)
__device__ __forceinline__ float gumbel_of(float u) {
    return -logf(-logf(u + 1e-9f) + 1e-9f);
}
// fast polynomial ln: range-reduce m in [2/3, 4/3), degree-7 Taylor.
__device__ __forceinline__ float fast_ln(float x) {
    const int i = __float_as_int(x);
    const int e = (i - 0x3f2aaaab) >> 23;            // arithmetic shift
    const float m = __int_as_float(i - (e << 23));   // in [2/3, 4/3)
    const float t = m - 1.0f;
    float p = -0.142857143f;
    p = fmaf(p, t, 0.166666667f);
    p = fmaf(p, t, -0.2f);
    p = fmaf(p, t, 0.25f);
    p = fmaf(p, t, -0.333333333f);
    p = fmaf(p, t, 0.5f);
    p = fmaf(p, t, -1.0f);
    return fmaf((float)e, 0.693147181f, -t * p);
}
__device__ __forceinline__ float gumbel_fast(float u) {
    const float v = -fast_ln(u + 1e-9f);
    return -fast_ln(v + 1e-9f);
}
__device__ __forceinline__ uint32_t pack_bf2(float a, float b) {
    return (uint32_t)__bfloat16_as_ushort(__float2bfloat16_rn(a))
         | ((uint32_t)__bfloat16_as_ushort(__float2bfloat16_rn(b)) << 16);
}
__device__ __forceinline__ float bf_bits2f(unsigned short v) {
    return __bfloat162float(__ushort_as_bfloat16(v));
}

// ---------------------------------------------------------------------------
// Kernel 0: fp32 -> bf16 cast (layout preserved). grid (2048, 2).
// ---------------------------------------------------------------------------
__global__ __launch_bounds__(256) void convert_kernel(
    const float* __restrict__ q, const float* __restrict__ k)
{
    const size_t e = ((size_t)blockIdx.x * 256 + threadIdx.x) * 8;
    const float* src = blockIdx.y ? k : q;
    __nv_bfloat16* dst = blockIdx.y ? g_ks : g_qs;
    float4 a = *(const float4*)(src + e);
    float4 b = *(const float4*)(src + e + 4);
    uint4 o;
    o.x = pack_bf2(a.x, a.y);
    o.y = pack_bf2(a.z, a.w);
    o.z = pack_bf2(b.x, b.y);
    o.w = pack_bf2(b.z, b.w);
    *(uint4*)(dst + e) = o;
}

// ---------------------------------------------------------------------------
// Kernel 1: 1-term bf16 mma.sync GEMM + fast gumbel -> z_approx (bf16).
// (unchanged from R14: 512 threads, warp tile 32x32, 2 CTAs/SM, 2-stage)
// ---------------------------------------------------------------------------
__global__ __launch_bounds__(512, 2) void gemm_approx_kernel(
    const float* __restrict__ u)
{
    extern __shared__ char smem[];
    const uint32_t sbase = smem_to_u32(smem);

    const int tid = threadIdx.x;
    const int lid = tid & 31;
    const int wid = tid >> 5;
    const int wm  = wid >> 2;
    const int wn  = wid & 3;

    const int b  = blockIdx.z;
    const int m0 = blockIdx.x * 128;
    const int n0 = blockIdx.y * 128;

    const int lrow  = (tid & 255) >> 1;
    const int lhalf = tid & 1;
    const __nv_bfloat16* lsrc0 = (tid < 256)
        ? g_qs + ((size_t)(b * H_) * N_ + (n0 + lrow)) * D_ + lhalf * 32
        : g_ks + ((size_t)(b * H_) * N_ + (m0 + lrow)) * D_ + lhalf * 32;
    const uint32_t my_tile = (tid < 256) ? 0u : 16384u;
    const size_t plane = (size_t)N_ * D_;

    float acc[2][4][4];
#pragma unroll
    for (int i = 0; i < 2; i++)
#pragma unroll
        for (int j = 0; j < 4; j++)
#pragma unroll
            for (int t = 0; t < 4; t++) acc[i][j][t] = 0.0f;

    const int ar = lid & 15;
    const int ac = lid >> 4;
    const int br = (lid & 7) + ((lid >> 4) << 3);
    const int bc = (lid >> 3) & 1;

    {
        const uint32_t dbase = sbase + my_tile;
#pragma unroll
        for (int c = 0; c < 4; c++)
            cp16(dbase + tile_off(lrow, lhalf * 4 + c), (const char*)lsrc0 + c * 16);
        cp_commit();
    }

#pragma unroll 1
    for (int it = 0; it < NIT; it++) {
        const int stg = it & 1;
        cp_wait<0>();
        __syncthreads();

        if (it + 1 < NIT) {
            const __nv_bfloat16* src = lsrc0 + (size_t)(it + 1) * plane;
            const uint32_t dbase = sbase + (uint32_t)((1 - stg) * STAGE_BYTES) + my_tile;
#pragma unroll
            for (int c = 0; c < 4; c++)
                cp16(dbase + tile_off(lrow, lhalf * 4 + c), (const char*)src + c * 16);
            cp_commit();
        }

        const uint32_t abase   = sbase + (uint32_t)(stg * STAGE_BYTES);
        const uint32_t bbase_s = abase + 16384u;

#pragma unroll
        for (int s = 0; s < 4; s++) {
            uint32_t ah[2][4], bb[2][4];
            ldsm4(ah[0], abase + tile_off(wm * 32 + ar, s * 2 + ac));
            ldsm4(ah[1], abase + tile_off(wm * 32 + 16 + ar, s * 2 + ac));
            ldsm4(bb[0], bbase_s + tile_off(wn * 32 + br, s * 2 + bc));
            ldsm4(bb[1], bbase_s + tile_off(wn * 32 + 16 + br, s * 2 + bc));
#pragma unroll
            for (int g = 0; g < 2; g++)
#pragma unroll
                for (int mf = 0; mf < 2; mf++) {
                    mma_bf16(acc[mf][g * 2 + 0], ah[mf], bb[g][0], bb[g][1]);
                    mma_bf16(acc[mf][g * 2 + 1], ah[mf], bb[g][2], bb[g][3]);
                }
        }
    }

    const int r4 = lid >> 2;
    const int c2 = (lid & 3) * 2;
#pragma unroll
    for (int mf = 0; mf < 2; mf++) {
#pragma unroll
        for (int rr = 0; rr < 2; rr++) {
            const int row = n0 + wm * 32 + mf * 16 + r4 + rr * 8;
            const size_t rbase = ((size_t)b * N_ + row) * N_ + m0 + wn * 32;
            const float* urow = u + rbase;
            unsigned short* zrow = g_zb + rbase;
#pragma unroll
            for (int j = 0; j < 4; j++) {
                const int co = (j >> 1) * 16 + (j & 1) * 8 + c2;
                float2 uv = *(const float2*)(urow + co);
                const float zx = acc[mf][j][rr * 2 + 0] * FSCALE + gumbel_fast(uv.x);
                const float zy = acc[mf][j][rr * 2 + 1] * FSCALE + gumbel_fast(uv.y);
                *(uint32_t*)(zrow + co) = pack_bf2(zx, zy);
            }
        }
    }
}

// ---------------------------------------------------------------------------
// Kernel 2: TWO rows per 512-thread block. 16-bit radix select (shared
// barriers for both rows) -> candidates within MARGIN -> exact fp32
// recompute -> exact 16th-largest -> mask.
// ---------------------------------------------------------------------------
__device__ __forceinline__ uint32_t bf2ord(unsigned short v) {
    return (v & 0x8000u) ? ((~(uint32_t)v) & 0xFFFFu) : ((uint32_t)v | 0x8000u);
}
__device__ __forceinline__ float ord2bf(uint32_t o) {
    unsigned short v = (o & 0x8000u) ? (unsigned short)(o & 0x7FFFu)
                                     : (unsigned short)((~o) & 0xFFFFu);
    return bf_bits2f(v);
}

__global__ __launch_bounds__(512) void topk_refine_kernel(
    const float* __restrict__ q, const float* __restrict__ k,
    const float* __restrict__ u, float* __restrict__ out)
{
    const int half = threadIdx.x >> 8;     // 0/1 -> which row of the pair
    const int t    = threadIdx.x & 255;    // thread within row group
    const int row  = blockIdx.x * 2 + half;
    const int b = row >> 11;               // pairs never straddle batches
    const int n = row & 2047;
    const int lid = threadIdx.x & 31;
    const int wid = threadIdx.x >> 5;      // 0..15

    __shared__ int      hist[2][256];
    __shared__ uint32_t s_prefix[2];
    __shared__ int      s_k[2];
    __shared__ float    qs[2][512];
    __shared__ int      scols[2][NCAND];
    __shared__ float    cand_z[2][NCAND];
    __shared__ int      scount[2];
    __shared__ float    s_thresh[2];

    // 8 consecutive bf16 z values per thread
    const unsigned short* zr = g_zb + (size_t)row * N_;
    uint4 rz = ((const uint4*)zr)[t];
    unsigned short vb[8] = {
        (unsigned short)(rz.x & 0xFFFF), (unsigned short)(rz.x >> 16),
        (unsigned short)(rz.y & 0xFFFF), (unsigned short)(rz.y >> 16),
        (unsigned short)(rz.z & 0xFFFF), (unsigned short)(rz.z >> 16),
        (unsigned short)(rz.w & 0xFFFF), (unsigned short)(rz.w >> 16)};
    uint32_t key[8];
    float vals[8];
#pragma unroll
    for (int j = 0; j < 8; j++) { key[j] = bf2ord(vb[j]); vals[j] = bf_bits2f(vb[j]); }

    // q row (512 floats) into smem
    {
        int c = t;
        qs[half][c] = q[(((size_t)(b * H_ + (c >> 6)) * N_ + n) << 6) + (c & 63)];
        c = t + 256;
        qs[half][c] = q[(((size_t)(b * H_ + (c >> 6)) * N_ + n) << 6) + (c & 63)];
    }
    if (t == 0) { s_prefix[half] = 0u; s_k[half] = KTOP; scount[half] = 0; }

    // 16-bit radix select, both rows sharing barriers
#pragma unroll
    for (int pass = 0; pass < 2; pass++) {
        const int shift = 8 - pass * 8;
        hist[half][t] = 0;
        __syncthreads();
        const uint32_t pref  = s_prefix[half];
        const int      kneed = s_k[half];
        const uint32_t hmask = (pass == 0) ? 0u : 0xFF00u;
#pragma unroll
        for (int j = 0; j < 8; j++)
            if ((key[j] & hmask) == pref)
                atomicAdd(&hist[half][(key[j] >> shift) & 255], 1);
        __syncthreads();

        if (wid == 0 || wid == 8) {        // one scan warp per row
            const int h = wid >> 3;
            const int base = lid * 8;
            int hh[8], ssum = 0;
#pragma unroll
            for (int j = 0; j < 8; j++) { hh[j] = hist[h][base + j]; ssum += hh[j]; }
            int suf = ssum;
#pragma unroll
            for (int off = 1; off < 32; off <<= 1) {
                int tt = __shfl_down_sync(0xffffffffu, suf, off);
                if (lid + off < 32) suf += tt;
            }
            int sufn = __shfl_down_sync(0xffffffffu, suf, 1);
            if (lid == 31) sufn = 0;
            const int kneed2 = s_k[h];
            if (suf >= kneed2 && sufn < kneed2) {
                int cum = sufn;
#pragma unroll
                for (int j = 7; j >= 0; j--) {
                    cum += hh[j];
                    if (cum >= kneed2) {
                        s_prefix[h] = s_prefix[h] | ((uint32_t)(base + j) << shift);
                        s_k[h]      = kneed2 - (cum - hh[j]);
                        break;
                    }
                }
            }
        }
        __syncthreads();
    }

    const float thr_lo = ord2bf(s_prefix[half]) - MARGIN;

    // candidate collect
#pragma unroll
    for (int j = 0; j < 8; j++) {
        if (vals[j] >= thr_lo) {
            int i = atomicAdd(&scount[half], 1);
            if (i < NCAND) scols[half][i] = t * 8 + j;
        }
    }
    __syncthreads();

    // exact fp32 recompute: warp w -> row (w&1), candidates (w>>1) + 8*round
    {
        const int r = wid & 1;
        const int cnt = (scount[r] < NCAND) ? scount[r] : NCAND;
        const int rr = blockIdx.x * 2 + r;
        const int bb2 = rr >> 11;
        const float* kb = k + (size_t)(bb2 * H_) * N_ * D_;
        for (int i = (wid >> 1); i < cnt; i += 8) {
            const int m = scols[r][i];
            float sum = 0.0f;
#pragma unroll
            for (int tt = 0; tt < 16; tt++) {
                const int c = lid + 32 * tt;
                sum += qs[r][c] * kb[(((size_t)(c >> 6) * N_ + m) << 6) + (c & 63)];
            }
#pragma unroll
            for (int off = 16; off; off >>= 1)
                sum += __shfl_xor_sync(0xffffffffu, sum, off);
            if (lid == 0)
                cand_z[r][i] = sum * FSCALE + gumbel_of(u[(size_t)rr * N_ + m]);
        }
    }
    __syncthreads();

    // exact 16th-largest among candidates (warp 0 -> row0, warp 8 -> row1)
    if (wid == 0 || wid == 8) {
        const int h = wid >> 3;
        const int cnt = (scount[h] < NCAND) ? scount[h] : NCAND;
        float va  = (lid < cnt) ? cand_z[h][lid] : -1e30f;
        float vb2 = (32 + lid < cnt) ? cand_z[h][32 + lid] : -1e30f;
        float vc  = (64 + lid < cnt) ? cand_z[h][64 + lid] : -1e30f;
        int ca = 0, cb = 0, cc = 0;
        for (int j = 0; j < cnt; j++) {
            const float w = cand_z[h][j];
            ca += (w >= va); cb += (w >= vb2); cc += (w >= vc);
        }
        float t1 = (ca >= KTOP && lid < cnt) ? va : -1e30f;
        float t2 = (cb >= KTOP && 32 + lid < cnt) ? vb2 : -1e30f;
        float t3 = (cc >= KTOP && 64 + lid < cnt) ? vc : -1e30f;
        float mx = fmaxf(fmaxf(t1, t2), t3);
#pragma unroll
        for (int off = 16; off; off >>= 1)
            mx = fmaxf(mx, __shfl_xor_sync(0xffffffffu, mx, off));
        if (lid == 0) s_thresh[h] = mx;
    }
    __syncthreads();

    // mask: zeros except candidates with exact z >= exact threshold
    const float thr = s_thresh[half];
    const int count = (scount[half] < NCAND) ? scount[half] : NCAND;
    float mk[8] = {0, 0, 0, 0, 0, 0, 0, 0};
    for (int i = 0; i < count; i++) {
        if (cand_z[half][i] >= thr) {
            const int rel = scols[half][i] - t * 8;
            if (rel >= 0 && rel < 8) mk[rel] = 1.0f;
        }
    }
    float* o = out + (size_t)row * N_ + t * 8;
    *(float4*)(o)     = make_float4(mk[0], mk[1], mk[2], mk[3]);
    *(float4*)(o + 4) = make_float4(mk[4], mk[5], mk[6], mk[7]);
}

// ---------------------------------------------------------------------------
extern "C" void kernel_launch(void* const* d_in, const int* in_sizes, int n_in,
                              void* d_out, int out_size)
{
    const float* q = (const float*)d_in[0];
    const float* k = (const float*)d_in[1];
    const float* u = (const float*)d_in[2];
    float* out = (float*)d_out;

    cudaFuncSetAttribute(gemm_approx_kernel,
                         cudaFuncAttributeMaxDynamicSharedMemorySize, SMEM_TOTAL);

    dim3 cgrid(2048, 2);
    convert_kernel<<<cgrid, 256>>>(q, k);
    dim3 ggrid(N_ / 128, N_ / 128, B_);
    gemm_approx_kernel<<<ggrid, 512, SMEM_TOTAL>>>(u);
    topk_refine_kernel<<<B_ * N_ / 2, 512>>>(q, k, u, out);
}